// round 1
// baseline (speedup 1.0000x reference)
#include <cuda_runtime.h>
#include <math.h>

#define BB 4
#define TT 2048
#define DD 1024
#define HH 16
#define HD 64
#define SCALE_F 0.125f   // 1/sqrt(64)

// Scratch: [B, H, T, hd] each
__device__ float g_q[(size_t)BB * HH * TT * HD];
__device__ float g_k[(size_t)BB * HH * TT * HD];
__device__ float g_v[(size_t)BB * HH * TT * HD];
__device__ float g_o[(size_t)BB * HH * TT * HD];

// ---------------------------------------------------------------------------
// Kernel 1: fused QKV projection. C = X @ W + b, written permuted into
// [B, H, T, hd]. BM=BN=64, BK=16, 256 threads, 4x4 per thread.
// blockIdx.x selects the head directly (BN == HD == 64).
// ---------------------------------------------------------------------------
__global__ __launch_bounds__(256) void qkv_gemm(
    const float* __restrict__ X,
    const float* __restrict__ Wq, const float* __restrict__ bq,
    const float* __restrict__ Wk, const float* __restrict__ bk,
    const float* __restrict__ Wv, const float* __restrict__ bv)
{
    const float* W;
    const float* bias;
    float* out;
    int z = blockIdx.z;
    if (z == 0)      { W = Wq; bias = bq; out = g_q; }
    else if (z == 1) { W = Wk; bias = bk; out = g_k; }
    else             { W = Wv; bias = bv; out = g_v; }

    __shared__ float As[16][64];   // [k][m]
    __shared__ float Bs[16][64];   // [k][n]

    int tid = threadIdx.x;
    int tx = tid & 15;        // 0..15 -> n
    int ty = tid >> 4;        // 0..15 -> m
    int m0 = blockIdx.y * 64;
    int n0 = blockIdx.x * 64;

    int ar = tid >> 2;               // 0..63 A row in tile
    int ak = (tid & 3) << 2;         // 0,4,8,12
    int brow = tid >> 4;             // 0..15 B row in tile
    int bn = (tid & 15) << 2;        // 0..60

    float acc[4][4];
#pragma unroll
    for (int i = 0; i < 4; i++)
#pragma unroll
        for (int j = 0; j < 4; j++) acc[i][j] = 0.f;

    for (int kt = 0; kt < DD; kt += 16) {
        float4 a = *(const float4*)&X[(size_t)(m0 + ar) * DD + kt + ak];
        As[ak + 0][ar] = a.x;
        As[ak + 1][ar] = a.y;
        As[ak + 2][ar] = a.z;
        As[ak + 3][ar] = a.w;
        float4 b = *(const float4*)&W[(size_t)(kt + brow) * DD + n0 + bn];
        *(float4*)&Bs[brow][bn] = b;
        __syncthreads();
#pragma unroll
        for (int k = 0; k < 16; k++) {
            float4 av = *(const float4*)&As[k][ty * 4];
            float4 bv4 = *(const float4*)&Bs[k][tx * 4];
            float avv[4] = {av.x, av.y, av.z, av.w};
            float bvv[4] = {bv4.x, bv4.y, bv4.z, bv4.w};
#pragma unroll
            for (int i = 0; i < 4; i++)
#pragma unroll
                for (int j = 0; j < 4; j++) acc[i][j] += avv[i] * bvv[j];
        }
        __syncthreads();
    }

    // Epilogue: permute into [B, H, T, hd]; head == blockIdx.x
    int head = blockIdx.x;
    float4 bb = *(const float4*)&bias[n0 + tx * 4];
#pragma unroll
    for (int i = 0; i < 4; i++) {
        int m = m0 + ty * 4 + i;
        int bI = m >> 11;       // m / 2048
        int t  = m & 2047;      // m % 2048
        float4 o;
        o.x = acc[i][0] + bb.x;
        o.y = acc[i][1] + bb.y;
        o.z = acc[i][2] + bb.z;
        o.w = acc[i][3] + bb.w;
        *(float4*)&out[(((size_t)bI * HH + head) * TT + t) * HD + tx * 4] = o;
    }
}

// ---------------------------------------------------------------------------
// Kernel 2: causal flash attention, fp32, online softmax.
// Grid: (T/128, B*H). 128 threads; 1 query per thread; key tiles of 32.
// ---------------------------------------------------------------------------
__global__ __launch_bounds__(128) void attn_kernel()
{
    int bh = blockIdx.y;
    int qt = blockIdx.x;
    int tid = threadIdx.x;
    int q_idx = qt * 128 + tid;

    const float* Qb = g_q + (size_t)bh * TT * HD;
    const float* Kb = g_k + (size_t)bh * TT * HD;
    const float* Vb = g_v + (size_t)bh * TT * HD;
    float* Ob       = g_o + (size_t)bh * TT * HD;

    float4 q[16];
#pragma unroll
    for (int i = 0; i < 16; i++)
        q[i] = *(const float4*)&Qb[(size_t)q_idx * HD + i * 4];

    float4 acc[16];
#pragma unroll
    for (int i = 0; i < 16; i++) acc[i] = make_float4(0.f, 0.f, 0.f, 0.f);

    float mrun = -INFINITY;
    float lrun = 0.f;

    __shared__ float4 Ks[32][16];
    __shared__ float4 Vs[32][16];

    int kend = qt * 128 + 128;
    for (int kt = 0; kt < kend; kt += 32) {
        __syncthreads();
#pragma unroll
        for (int i = 0; i < 4; i++) {
            int idx = tid + i * 128;    // 0..511
            int r = idx >> 4;
            int c = idx & 15;
            Ks[r][c] = *(const float4*)&Kb[(size_t)(kt + r) * HD + c * 4];
            Vs[r][c] = *(const float4*)&Vb[(size_t)(kt + r) * HD + c * 4];
        }
        __syncthreads();

        // scores
        float s[32];
#pragma unroll
        for (int n = 0; n < 32; n++) s[n] = 0.f;
#pragma unroll
        for (int k4 = 0; k4 < 16; k4++) {
            float4 qv = q[k4];
#pragma unroll
            for (int n = 0; n < 32; n++) {
                float4 kv = Ks[n][k4];
                s[n] += qv.x * kv.x + qv.y * kv.y + qv.z * kv.z + qv.w * kv.w;
            }
        }

        // scale + causal mask + running max
        float mt = mrun;
        bool need_mask = (kt + 31 > q_idx);
#pragma unroll
        for (int n = 0; n < 32; n++) {
            float sv = s[n] * SCALE_F;
            if (need_mask && (kt + n > q_idx)) sv = -INFINITY;
            s[n] = sv;
            mt = fmaxf(mt, sv);
        }

        float alpha = (mrun == -INFINITY) ? 0.f : __expf(mrun - mt);
        float psum = 0.f;
#pragma unroll
        for (int n = 0; n < 32; n++) {
            float p = __expf(s[n] - mt);
            s[n] = p;
            psum += p;
        }
        lrun = lrun * alpha + psum;
#pragma unroll
        for (int i = 0; i < 16; i++) {
            acc[i].x *= alpha;
            acc[i].y *= alpha;
            acc[i].z *= alpha;
            acc[i].w *= alpha;
        }
#pragma unroll
        for (int n = 0; n < 32; n++) {
            float p = s[n];
#pragma unroll
            for (int k4 = 0; k4 < 16; k4++) {
                float4 vv = Vs[n][k4];
                acc[k4].x += p * vv.x;
                acc[k4].y += p * vv.y;
                acc[k4].z += p * vv.z;
                acc[k4].w += p * vv.w;
            }
        }
        mrun = mt;
    }

    float inv = 1.f / lrun;
#pragma unroll
    for (int i = 0; i < 16; i++) {
        float4 o;
        o.x = acc[i].x * inv;
        o.y = acc[i].y * inv;
        o.z = acc[i].z * inv;
        o.w = acc[i].w * inv;
        *(float4*)&Ob[(size_t)q_idx * HD + i * 4] = o;
    }
}

// ---------------------------------------------------------------------------
// Kernel 3: output projection. A = g_o gathered from [B,H,T,hd] as
// [B*T, D] row-major logical; C = A @ Wo + bo -> d_out [B,T,D].
// ---------------------------------------------------------------------------
__global__ __launch_bounds__(256) void out_proj(
    const float* __restrict__ Wo, const float* __restrict__ bo,
    float* __restrict__ out)
{
    __shared__ float As[16][64];
    __shared__ float Bs[16][64];

    int tid = threadIdx.x;
    int tx = tid & 15;
    int ty = tid >> 4;
    int m0 = blockIdx.y * 64;
    int n0 = blockIdx.x * 64;

    int ar = tid >> 2;
    int ak = (tid & 3) << 2;
    int brow = tid >> 4;
    int bn = (tid & 15) << 2;

    // gather coords for A load (constant across k-loop except head/d)
    int m = m0 + ar;
    int bI = m >> 11;
    int t  = m & 2047;

    float acc[4][4];
#pragma unroll
    for (int i = 0; i < 4; i++)
#pragma unroll
        for (int j = 0; j < 4; j++) acc[i][j] = 0.f;

    for (int kt = 0; kt < DD; kt += 16) {
        int kk = kt + ak;
        int h = kk >> 6;
        int d = kk & 63;
        float4 a = *(const float4*)&g_o[(((size_t)bI * HH + h) * TT + t) * HD + d];
        As[ak + 0][ar] = a.x;
        As[ak + 1][ar] = a.y;
        As[ak + 2][ar] = a.z;
        As[ak + 3][ar] = a.w;
        float4 b = *(const float4*)&Wo[(size_t)(kt + brow) * DD + n0 + bn];
        *(float4*)&Bs[brow][bn] = b;
        __syncthreads();
#pragma unroll
        for (int k = 0; k < 16; k++) {
            float4 av = *(const float4*)&As[k][ty * 4];
            float4 bv4 = *(const float4*)&Bs[k][tx * 4];
            float avv[4] = {av.x, av.y, av.z, av.w};
            float bvv[4] = {bv4.x, bv4.y, bv4.z, bv4.w};
#pragma unroll
            for (int i = 0; i < 4; i++)
#pragma unroll
                for (int j = 0; j < 4; j++) acc[i][j] += avv[i] * bvv[j];
        }
        __syncthreads();
    }

    float4 bb = *(const float4*)&bo[n0 + tx * 4];
#pragma unroll
    for (int i = 0; i < 4; i++) {
        int mm = m0 + ty * 4 + i;
        float4 o;
        o.x = acc[i][0] + bb.x;
        o.y = acc[i][1] + bb.y;
        o.z = acc[i][2] + bb.z;
        o.w = acc[i][3] + bb.w;
        *(float4*)&out[(size_t)mm * DD + n0 + tx * 4] = o;
    }
}

extern "C" void kernel_launch(void* const* d_in, const int* in_sizes, int n_in,
                              void* d_out, int out_size)
{
    const float* x  = (const float*)d_in[0];
    const float* Wq = (const float*)d_in[1];
    const float* bq = (const float*)d_in[2];
    const float* Wk = (const float*)d_in[3];
    const float* bk = (const float*)d_in[4];
    const float* Wv = (const float*)d_in[5];
    const float* bv = (const float*)d_in[6];
    const float* Wo = (const float*)d_in[7];
    const float* bo = (const float*)d_in[8];
    float* out = (float*)d_out;

    dim3 g1(DD / 64, (BB * TT) / 64, 3);   // 16 x 128 x 3
    qkv_gemm<<<g1, 256>>>(x, Wq, bq, Wk, bk, Wv, bv);

    dim3 g2(TT / 128, BB * HH);            // 16 x 64
    attn_kernel<<<g2, 128>>>();

    dim3 g3(DD / 64, (BB * TT) / 64);      // 16 x 128
    out_proj<<<g3, 256>>>(Wo, bo, out);
}

// round 4
// speedup vs baseline: 1.5928x; 1.5928x over previous
#include <cuda_runtime.h>
#include <math.h>
#include <stdint.h>

#define BB 4
#define TT 2048
#define DD 1024
#define HH 16
#define HD 64
#define SCALE_F 0.125f   // 1/sqrt(64)

// Scratch: [B, H, T, hd] each
__device__ float g_q[(size_t)BB * HH * TT * HD];
__device__ float g_k[(size_t)BB * HH * TT * HD];
__device__ float g_v[(size_t)BB * HH * TT * HD];
__device__ float g_o[(size_t)BB * HH * TT * HD];
// W^T scratch: 4 matrices [N=1024][K=1024], tf32-rounded
__device__ float g_wt[(size_t)4 * DD * DD];

__device__ __forceinline__ uint32_t f2tf32(float f) {
    uint32_t r;
    asm("cvt.rna.tf32.f32 %0, %1;" : "=r"(r) : "f"(f));
    return r;
}

__device__ __forceinline__ void mma_tf32(float* d, const uint32_t* a,
                                         const uint32_t* b) {
    asm volatile(
        "mma.sync.aligned.m16n8k8.row.col.f32.tf32.tf32.f32 "
        "{%0,%1,%2,%3}, {%4,%5,%6,%7}, {%8,%9}, {%0,%1,%2,%3};"
        : "+f"(d[0]), "+f"(d[1]), "+f"(d[2]), "+f"(d[3])
        : "r"(a[0]), "r"(a[1]), "r"(a[2]), "r"(a[3]),
          "r"(b[0]), "r"(b[1]));
}

// ---------------------------------------------------------------------------
// Weight transpose: W [K,N] -> g_wt slice [N,K], tf32-rounded
// grid (32,32,4), block (32,8)
// ---------------------------------------------------------------------------
__global__ __launch_bounds__(256) void transpose_w(
    const float* __restrict__ Wq, const float* __restrict__ Wk,
    const float* __restrict__ Wv, const float* __restrict__ Wo)
{
    const float* src = (blockIdx.z == 0) ? Wq : (blockIdx.z == 1) ? Wk
                     : (blockIdx.z == 2) ? Wv : Wo;
    float* dst = g_wt + (size_t)blockIdx.z * DD * DD;

    __shared__ float tile[32][33];
    int x = blockIdx.x * 32 + threadIdx.x;  // n
    int y0 = blockIdx.y * 32;               // k base
#pragma unroll
    for (int j = threadIdx.y; j < 32; j += 8)
        tile[j][threadIdx.x] = src[(size_t)(y0 + j) * DD + x];
    __syncthreads();
    int x2 = y0 + threadIdx.x;              // k
    int y2 = blockIdx.x * 32;               // n base
#pragma unroll
    for (int j = threadIdx.y; j < 32; j += 8)
        dst[(size_t)(y2 + j) * DD + x2] = __uint_as_float(f2tf32(tile[threadIdx.x][j]));
}

// ---------------------------------------------------------------------------
// tf32 mma.sync GEMM: C[128x128 tile] = A @ Wt^T (+bias)
// MODE 0: A = X [B*T, D] (arg), out permuted into g_q/g_k/g_v [B,H,T,hd]
//         (blockIdx.z selects matrix)
// MODE 1: A gathered from g_o (device symbol, NOT an argument), out = d_out
// 256 threads = 8 warps, warp grid 2(m) x 4(n), warp tile 64x32.
// Smem tiles padded to stride 36 floats -> conflict-free fragment loads.
// ---------------------------------------------------------------------------
#define BK 32
#define ASTRIDE 36

template <int MODE>
__global__ __launch_bounds__(256) void gemm_tc(
    const float* __restrict__ Asrc,   // MODE 0: x. MODE 1: unused (nullptr)
    const float* __restrict__ b0, const float* __restrict__ b1,
    const float* __restrict__ b2, float* __restrict__ OutDirect)
{
    __shared__ float sA[128 * ASTRIDE];
    __shared__ float sB[128 * ASTRIDE];

    int tid = threadIdx.x;
    int wid = tid >> 5;
    int lane = tid & 31;
    int warp_m = wid & 1;       // 0..1
    int warp_n = wid >> 1;      // 0..3
    int r = lane >> 2;          // 0..7
    int c = lane & 3;           // 0..3
    int n0 = blockIdx.x * 128;
    int m0 = blockIdx.y * 128;

    const float* Wt;
    const float* bias;
    float* out;
    const float* Ain;
    if (MODE == 0) {
        int z = blockIdx.z;
        Wt = g_wt + (size_t)z * DD * DD;
        bias = (z == 0) ? b0 : (z == 1) ? b1 : b2;
        out = (z == 0) ? g_q : (z == 1) ? g_k : g_v;
        Ain = Asrc;
    } else {
        Wt = g_wt + (size_t)3 * DD * DD;
        bias = b0;
        out = OutDirect;
        Ain = g_o;              // device symbol referenced from device code
    }

    float acc[4][4][4];
#pragma unroll
    for (int mt = 0; mt < 4; mt++)
#pragma unroll
        for (int nt = 0; nt < 4; nt++)
#pragma unroll
            for (int i = 0; i < 4; i++) acc[mt][nt][i] = 0.f;

    for (int kt = 0; kt < DD; kt += BK) {
        // ---- global -> smem (A tf32-rounded; B already tf32) ----
#pragma unroll
        for (int i = 0; i < 4; i++) {
            int idx = tid + i * 256;        // 0..1023
            int row = idx >> 3;             // 0..127
            int c4 = idx & 7;               // 0..7
            const float* srcp;
            if (MODE == 0) {
                srcp = Ain + (size_t)(m0 + row) * DD + kt + c4 * 4;
            } else {
                int m = m0 + row;
                int b = m >> 11;
                int t = m & 2047;
                int h = kt >> 6;
                int d0 = (kt & 63) + c4 * 4;
                srcp = Ain + (((size_t)b * HH + h) * TT + t) * HD + d0;
            }
            float4 v = *(const float4*)srcp;
            uint4 u;
            u.x = f2tf32(v.x); u.y = f2tf32(v.y);
            u.z = f2tf32(v.z); u.w = f2tf32(v.w);
            *(uint4*)&sA[row * ASTRIDE + c4 * 4] = u;

            float4 w = *(const float4*)(Wt + (size_t)(n0 + row) * DD + kt + c4 * 4);
            *(float4*)&sB[row * ASTRIDE + c4 * 4] = w;
        }
        __syncthreads();

        // ---- 4 k-slices of 8 ----
#pragma unroll
        for (int ks = 0; ks < 4; ks++) {
            int k0 = ks * 8;
            uint32_t af[4][4], bf[4][2];
#pragma unroll
            for (int mt = 0; mt < 4; mt++) {
                const float* base = &sA[(warp_m * 64 + mt * 16 + r) * ASTRIDE + k0 + c];
                af[mt][0] = __float_as_uint(base[0]);
                af[mt][1] = __float_as_uint(base[8 * ASTRIDE]);
                af[mt][2] = __float_as_uint(base[4]);
                af[mt][3] = __float_as_uint(base[8 * ASTRIDE + 4]);
            }
#pragma unroll
            for (int nt = 0; nt < 4; nt++) {
                const float* base = &sB[(warp_n * 32 + nt * 8 + r) * ASTRIDE + k0 + c];
                bf[nt][0] = __float_as_uint(base[0]);
                bf[nt][1] = __float_as_uint(base[4]);
            }
#pragma unroll
            for (int mt = 0; mt < 4; mt++)
#pragma unroll
                for (int nt = 0; nt < 4; nt++)
                    mma_tf32(acc[mt][nt], af[mt], bf[nt]);
        }
        __syncthreads();
    }

    // ---- epilogue: direct float2 stores from C fragments ----
#pragma unroll
    for (int nt = 0; nt < 4; nt++) {
        int col = n0 + warp_n * 32 + nt * 8 + c * 2;
        float bx = __ldg(&bias[col]);
        float by = __ldg(&bias[col + 1]);
#pragma unroll
        for (int mt = 0; mt < 4; mt++) {
            int row0 = m0 + warp_m * 64 + mt * 16 + r;
            float2 v0, v1;
            v0.x = acc[mt][nt][0] + bx;
            v0.y = acc[mt][nt][1] + by;
            v1.x = acc[mt][nt][2] + bx;
            v1.y = acc[mt][nt][3] + by;
            if (MODE == 0) {
                int head = col >> 6;
                int d = col & 63;
                int b = row0 >> 11;
                int t = row0 & 2047;
                size_t base = (((size_t)b * HH + head) * TT + t) * HD + d;
                *(float2*)&out[base] = v0;
                // row0+8 is same b (rows within 16-block never cross batch: 2048%16==0)
                *(float2*)&out[base + 8 * HD] = v1;
            } else {
                *(float2*)&out[(size_t)row0 * DD + col] = v0;
                *(float2*)&out[(size_t)(row0 + 8) * DD + col] = v1;
            }
        }
    }
}

// ---------------------------------------------------------------------------
// Kernel 2: causal flash attention, fp32, online softmax (unchanged).
// Grid: (T/128, B*H). 128 threads; 1 query per thread; key tiles of 32.
// ---------------------------------------------------------------------------
__global__ __launch_bounds__(128) void attn_kernel()
{
    int bh = blockIdx.y;
    int qt = blockIdx.x;
    int tid = threadIdx.x;
    int q_idx = qt * 128 + tid;

    const float* Qb = g_q + (size_t)bh * TT * HD;
    const float* Kb = g_k + (size_t)bh * TT * HD;
    const float* Vb = g_v + (size_t)bh * TT * HD;
    float* Ob       = g_o + (size_t)bh * TT * HD;

    float4 q[16];
#pragma unroll
    for (int i = 0; i < 16; i++)
        q[i] = *(const float4*)&Qb[(size_t)q_idx * HD + i * 4];

    float4 acc[16];
#pragma unroll
    for (int i = 0; i < 16; i++) acc[i] = make_float4(0.f, 0.f, 0.f, 0.f);

    float mrun = -INFINITY;
    float lrun = 0.f;

    __shared__ float4 Ks[32][16];
    __shared__ float4 Vs[32][16];

    int kend = qt * 128 + 128;
    for (int kt = 0; kt < kend; kt += 32) {
        __syncthreads();
#pragma unroll
        for (int i = 0; i < 4; i++) {
            int idx = tid + i * 128;
            int rr = idx >> 4;
            int cc = idx & 15;
            Ks[rr][cc] = *(const float4*)&Kb[(size_t)(kt + rr) * HD + cc * 4];
            Vs[rr][cc] = *(const float4*)&Vb[(size_t)(kt + rr) * HD + cc * 4];
        }
        __syncthreads();

        float s[32];
#pragma unroll
        for (int n = 0; n < 32; n++) s[n] = 0.f;
#pragma unroll
        for (int k4 = 0; k4 < 16; k4++) {
            float4 qv = q[k4];
#pragma unroll
            for (int n = 0; n < 32; n++) {
                float4 kv = Ks[n][k4];
                s[n] += qv.x * kv.x + qv.y * kv.y + qv.z * kv.z + qv.w * kv.w;
            }
        }

        float mt = mrun;
        bool need_mask = (kt + 31 > q_idx);
#pragma unroll
        for (int n = 0; n < 32; n++) {
            float sv = s[n] * SCALE_F;
            if (need_mask && (kt + n > q_idx)) sv = -INFINITY;
            s[n] = sv;
            mt = fmaxf(mt, sv);
        }

        float alpha = (mrun == -INFINITY) ? 0.f : __expf(mrun - mt);
        float psum = 0.f;
#pragma unroll
        for (int n = 0; n < 32; n++) {
            float p = __expf(s[n] - mt);
            s[n] = p;
            psum += p;
        }
        lrun = lrun * alpha + psum;
#pragma unroll
        for (int i = 0; i < 16; i++) {
            acc[i].x *= alpha;
            acc[i].y *= alpha;
            acc[i].z *= alpha;
            acc[i].w *= alpha;
        }
#pragma unroll
        for (int n = 0; n < 32; n++) {
            float p = s[n];
#pragma unroll
            for (int k4 = 0; k4 < 16; k4++) {
                float4 vv = Vs[n][k4];
                acc[k4].x += p * vv.x;
                acc[k4].y += p * vv.y;
                acc[k4].z += p * vv.z;
                acc[k4].w += p * vv.w;
            }
        }
        mrun = mt;
    }

    float inv = 1.f / lrun;
#pragma unroll
    for (int i = 0; i < 16; i++) {
        float4 o;
        o.x = acc[i].x * inv;
        o.y = acc[i].y * inv;
        o.z = acc[i].z * inv;
        o.w = acc[i].w * inv;
        *(float4*)&Ob[(size_t)q_idx * HD + i * 4] = o;
    }
}

extern "C" void kernel_launch(void* const* d_in, const int* in_sizes, int n_in,
                              void* d_out, int out_size)
{
    const float* x  = (const float*)d_in[0];
    const float* Wq = (const float*)d_in[1];
    const float* bq = (const float*)d_in[2];
    const float* Wk = (const float*)d_in[3];
    const float* bk = (const float*)d_in[4];
    const float* Wv = (const float*)d_in[5];
    const float* bv = (const float*)d_in[6];
    const float* Wo = (const float*)d_in[7];
    const float* bo = (const float*)d_in[8];
    float* out = (float*)d_out;

    dim3 gt(32, 32, 4);
    transpose_w<<<gt, dim3(32, 8)>>>(Wq, Wk, Wv, Wo);

    dim3 g1(DD / 128, (BB * TT) / 128, 3);   // 8 x 64 x 3
    gemm_tc<0><<<g1, 256>>>(x, bq, bk, bv, nullptr);

    dim3 g2(TT / 128, BB * HH);              // 16 x 64
    attn_kernel<<<g2, 128>>>();

    dim3 g3(DD / 128, (BB * TT) / 128);      // 8 x 64
    gemm_tc<1><<<g3, 256>>>(nullptr, bo, nullptr, nullptr, out);
}

// round 5
// speedup vs baseline: 4.6388x; 2.9124x over previous
#include <cuda_runtime.h>
#include <math.h>
#include <stdint.h>

#define BB 4
#define TT 2048
#define DD 1024
#define HH 16
#define HD 64
#define SCALE_F 0.125f   // 1/sqrt(64)

// Scratch. g_q, g_k, g_o: [B, H, T, hd]. g_v: [B, H, hd, T] (TRANSPOSED).
__device__ float g_q[(size_t)BB * HH * TT * HD];
__device__ float g_k[(size_t)BB * HH * TT * HD];
__device__ float g_v[(size_t)BB * HH * TT * HD];
__device__ float g_o[(size_t)BB * HH * TT * HD];
// W^T scratch: 4 matrices [N=1024][K=1024], tf32-rounded
__device__ float g_wt[(size_t)4 * DD * DD];

__device__ __forceinline__ uint32_t f2tf32(float f) {
    uint32_t r;
    asm("cvt.rna.tf32.f32 %0, %1;" : "=r"(r) : "f"(f));
    return r;
}
__device__ __forceinline__ float rtf32(float f) {
    return __uint_as_float(f2tf32(f));
}

__device__ __forceinline__ void mma_tf32(float* d, const uint32_t* a,
                                         const uint32_t* b) {
    asm volatile(
        "mma.sync.aligned.m16n8k8.row.col.f32.tf32.tf32.f32 "
        "{%0,%1,%2,%3}, {%4,%5,%6,%7}, {%8,%9}, {%0,%1,%2,%3};"
        : "+f"(d[0]), "+f"(d[1]), "+f"(d[2]), "+f"(d[3])
        : "r"(a[0]), "r"(a[1]), "r"(a[2]), "r"(a[3]),
          "r"(b[0]), "r"(b[1]));
}

// XOR swizzle for 64-col fp32 tiles: conflict-free fragment access
#define SW(row, col) (((row) << 6) + ((col) ^ (((row) & 7) << 2)))

// ---------------------------------------------------------------------------
// Weight transpose: W [K,N] -> g_wt slice [N,K], tf32-rounded
// ---------------------------------------------------------------------------
__global__ __launch_bounds__(256) void transpose_w(
    const float* __restrict__ Wq, const float* __restrict__ Wk,
    const float* __restrict__ Wv, const float* __restrict__ Wo)
{
    const float* src = (blockIdx.z == 0) ? Wq : (blockIdx.z == 1) ? Wk
                     : (blockIdx.z == 2) ? Wv : Wo;
    float* dst = g_wt + (size_t)blockIdx.z * DD * DD;

    __shared__ float tile[32][33];
    int x = blockIdx.x * 32 + threadIdx.x;  // n
    int y0 = blockIdx.y * 32;               // k base
#pragma unroll
    for (int j = threadIdx.y; j < 32; j += 8)
        tile[j][threadIdx.x] = src[(size_t)(y0 + j) * DD + x];
    __syncthreads();
    int x2 = y0 + threadIdx.x;              // k
    int y2 = blockIdx.x * 32;               // n base
#pragma unroll
    for (int j = threadIdx.y; j < 32; j += 8)
        dst[(size_t)(y2 + j) * DD + x2] = rtf32(tile[threadIdx.x][j]);
}

// ---------------------------------------------------------------------------
// tf32 mma.sync GEMM: C[128x128 tile] = A @ Wt^T (+bias)
// MODE 0: A = X; z=0 -> g_q [B,H,T,hd], z=1 -> g_k [B,H,T,hd],
//         z=2 -> g_v TRANSPOSED [B,H,hd,T]
// MODE 1: A gathered from g_o (device symbol), out = d_out [B*T, D]
// ---------------------------------------------------------------------------
#define BK 32
#define ASTRIDE 36

template <int MODE>
__global__ __launch_bounds__(256) void gemm_tc(
    const float* __restrict__ Asrc,
    const float* __restrict__ b0, const float* __restrict__ b1,
    const float* __restrict__ b2, float* __restrict__ OutDirect)
{
    __shared__ float sA[128 * ASTRIDE];
    __shared__ float sB[128 * ASTRIDE];

    int tid = threadIdx.x;
    int wid = tid >> 5;
    int lane = tid & 31;
    int warp_m = wid & 1;
    int warp_n = wid >> 1;
    int r = lane >> 2;
    int c = lane & 3;
    int n0 = blockIdx.x * 128;
    int m0 = blockIdx.y * 128;

    const float* Wt;
    const float* bias;
    float* out;
    const float* Ain;
    int zsel = 0;
    if (MODE == 0) {
        zsel = blockIdx.z;
        Wt = g_wt + (size_t)zsel * DD * DD;
        bias = (zsel == 0) ? b0 : (zsel == 1) ? b1 : b2;
        out = (zsel == 0) ? g_q : (zsel == 1) ? g_k : g_v;
        Ain = Asrc;
    } else {
        Wt = g_wt + (size_t)3 * DD * DD;
        bias = b0;
        out = OutDirect;
        Ain = g_o;
    }

    float acc[4][4][4];
#pragma unroll
    for (int mt = 0; mt < 4; mt++)
#pragma unroll
        for (int nt = 0; nt < 4; nt++)
#pragma unroll
            for (int i = 0; i < 4; i++) acc[mt][nt][i] = 0.f;

    for (int kt = 0; kt < DD; kt += BK) {
#pragma unroll
        for (int i = 0; i < 4; i++) {
            int idx = tid + i * 256;
            int row = idx >> 3;
            int c4 = idx & 7;
            const float* srcp;
            if (MODE == 0) {
                srcp = Ain + (size_t)(m0 + row) * DD + kt + c4 * 4;
            } else {
                int m = m0 + row;
                int b = m >> 11;
                int t = m & 2047;
                int h = kt >> 6;
                int d0 = (kt & 63) + c4 * 4;
                srcp = Ain + (((size_t)b * HH + h) * TT + t) * HD + d0;
            }
            float4 v = *(const float4*)srcp;
            uint4 u;
            u.x = f2tf32(v.x); u.y = f2tf32(v.y);
            u.z = f2tf32(v.z); u.w = f2tf32(v.w);
            *(uint4*)&sA[row * ASTRIDE + c4 * 4] = u;

            float4 w = *(const float4*)(Wt + (size_t)(n0 + row) * DD + kt + c4 * 4);
            *(float4*)&sB[row * ASTRIDE + c4 * 4] = w;
        }
        __syncthreads();

#pragma unroll
        for (int ks = 0; ks < 4; ks++) {
            int k0 = ks * 8;
            uint32_t af[4][4], bf[4][2];
#pragma unroll
            for (int mt = 0; mt < 4; mt++) {
                const float* base = &sA[(warp_m * 64 + mt * 16 + r) * ASTRIDE + k0 + c];
                af[mt][0] = __float_as_uint(base[0]);
                af[mt][1] = __float_as_uint(base[8 * ASTRIDE]);
                af[mt][2] = __float_as_uint(base[4]);
                af[mt][3] = __float_as_uint(base[8 * ASTRIDE + 4]);
            }
#pragma unroll
            for (int nt = 0; nt < 4; nt++) {
                const float* base = &sB[(warp_n * 32 + nt * 8 + r) * ASTRIDE + k0 + c];
                bf[nt][0] = __float_as_uint(base[0]);
                bf[nt][1] = __float_as_uint(base[4]);
            }
#pragma unroll
            for (int mt = 0; mt < 4; mt++)
#pragma unroll
                for (int nt = 0; nt < 4; nt++)
                    mma_tf32(acc[mt][nt], af[mt], bf[nt]);
        }
        __syncthreads();
    }

#pragma unroll
    for (int nt = 0; nt < 4; nt++) {
        int col = n0 + warp_n * 32 + nt * 8 + c * 2;
        float bx = __ldg(&bias[col]);
        float by = __ldg(&bias[col + 1]);
#pragma unroll
        for (int mt = 0; mt < 4; mt++) {
            int row0 = m0 + warp_m * 64 + mt * 16 + r;
            float2 v0, v1;
            v0.x = acc[mt][nt][0] + bx;
            v0.y = acc[mt][nt][1] + by;
            v1.x = acc[mt][nt][2] + bx;
            v1.y = acc[mt][nt][3] + by;
            if (MODE == 0) {
                int head = col >> 6;
                int d = col & 63;
                int b = row0 >> 11;
                int t = row0 & 2047;
                if (zsel == 2) {
                    // V transposed: [B,H,hd,T]
                    size_t vb = ((size_t)b * HH + head) * HD;
                    out[(vb + d) * TT + t] = v0.x;
                    out[(vb + d + 1) * TT + t] = v0.y;
                    out[(vb + d) * TT + t + 8] = v1.x;
                    out[(vb + d + 1) * TT + t + 8] = v1.y;
                } else {
                    size_t base = (((size_t)b * HH + head) * TT + t) * HD + d;
                    *(float2*)&out[base] = v0;
                    *(float2*)&out[base + 8 * HD] = v1;
                }
            } else {
                *(float2*)&out[(size_t)row0 * DD + col] = v0;
                *(float2*)&out[(size_t)(row0 + 8) * DD + col] = v1;
            }
        }
    }
}

// ---------------------------------------------------------------------------
// Tensor-core causal flash attention.
// Grid (T/64, B*H), 128 threads = 4 warps, each warp owns 16 query rows.
// 64-key iterations; S = Q K^T and O += P V via m16n8k8 tf32 mma.
// Smem: 3 x 64x64 fp32 tiles, XOR-swizzled, exactly 48KB.
// sQP holds Q during prologue, then reused per-warp as the P buffer.
// ---------------------------------------------------------------------------
__global__ __launch_bounds__(128) void attn_tc()
{
    __shared__ float sm[3 * 64 * 64];
    float* sQP = sm;
    float* sK  = sm + 4096;
    float* sVt = sm + 8192;

    int bh = blockIdx.y;
    int m0 = blockIdx.x * 64;
    int tid = threadIdx.x;
    int wid = tid >> 5;
    int lane = tid & 31;
    int r = lane >> 2;
    int c = lane & 3;

    const float* Qb  = g_q + (size_t)bh * TT * HD;
    const float* Kb  = g_k + (size_t)bh * TT * HD;
    const float* Vtb = g_v + (size_t)bh * HD * TT;   // [d][T]
    float* Ob        = g_o + (size_t)bh * TT * HD;

    // ---- Q tile -> smem (rounded), then per-warp fragments ----
#pragma unroll
    for (int i = 0; i < 8; i++) {
        int idx = tid + i * 128;
        int row = idx >> 4;
        int c4 = idx & 15;
        float4 v = *(const float4*)&Qb[(size_t)(m0 + row) * HD + c4 * 4];
        v.x = rtf32(v.x); v.y = rtf32(v.y); v.z = rtf32(v.z); v.w = rtf32(v.w);
        *(float4*)&sQP[SW(row, c4 * 4)] = v;
    }
    __syncthreads();

    int lrow = wid * 16 + r;
    float qf[8][4];
#pragma unroll
    for (int kc = 0; kc < 8; kc++) {
        qf[kc][0] = sQP[SW(lrow,     kc * 8 + c)];
        qf[kc][1] = sQP[SW(lrow + 8, kc * 8 + c)];
        qf[kc][2] = sQP[SW(lrow,     kc * 8 + c + 4)];
        qf[kc][3] = sQP[SW(lrow + 8, kc * 8 + c + 4)];
    }
    // warps only touch their own 16-row band of sQP from here on

    float o[8][4];
#pragma unroll
    for (int nt = 0; nt < 8; nt++)
#pragma unroll
        for (int i = 0; i < 4; i++) o[nt][i] = 0.f;

    float mr0 = -INFINITY, mr1 = -INFINITY;
    float l0 = 0.f, l1 = 0.f;
    int rg0 = m0 + lrow;
    int rg1 = rg0 + 8;

    for (int kt = 0; kt <= m0; kt += 64) {
        // ---- cooperative K / V^T tile loads (rounded) ----
#pragma unroll
        for (int i = 0; i < 8; i++) {
            int idx = tid + i * 128;
            int row = idx >> 4;
            int c4 = idx & 15;
            float4 kv = *(const float4*)&Kb[(size_t)(kt + row) * HD + c4 * 4];
            kv.x = rtf32(kv.x); kv.y = rtf32(kv.y);
            kv.z = rtf32(kv.z); kv.w = rtf32(kv.w);
            *(float4*)&sK[SW(row, c4 * 4)] = kv;
            float4 vv = *(const float4*)&Vtb[(size_t)row * TT + kt + c4 * 4];
            vv.x = rtf32(vv.x); vv.y = rtf32(vv.y);
            vv.z = rtf32(vv.z); vv.w = rtf32(vv.w);
            *(float4*)&sVt[SW(row, c4 * 4)] = vv;
        }
        __syncthreads();

        // ---- S = Q K^T ----
        float s[8][4];
#pragma unroll
        for (int nt = 0; nt < 8; nt++)
#pragma unroll
            for (int i = 0; i < 4; i++) s[nt][i] = 0.f;
#pragma unroll
        for (int kc = 0; kc < 8; kc++) {
            uint32_t af[4];
            af[0] = __float_as_uint(qf[kc][0]);
            af[1] = __float_as_uint(qf[kc][1]);
            af[2] = __float_as_uint(qf[kc][2]);
            af[3] = __float_as_uint(qf[kc][3]);
#pragma unroll
            for (int nt = 0; nt < 8; nt++) {
                uint32_t bf[2];
                bf[0] = __float_as_uint(sK[SW(nt * 8 + r, kc * 8 + c)]);
                bf[1] = __float_as_uint(sK[SW(nt * 8 + r, kc * 8 + c + 4)]);
                mma_tf32(s[nt], af, bf);
            }
        }

        // ---- scale, mask, online softmax ----
        float mx0 = mr0, mx1 = mr1;
        bool diag = (kt == m0);
#pragma unroll
        for (int nt = 0; nt < 8; nt++) {
            s[nt][0] *= SCALE_F; s[nt][1] *= SCALE_F;
            s[nt][2] *= SCALE_F; s[nt][3] *= SCALE_F;
            if (diag) {
                int col0 = kt + nt * 8 + 2 * c;
                if (col0     > rg0) s[nt][0] = -INFINITY;
                if (col0 + 1 > rg0) s[nt][1] = -INFINITY;
                if (col0     > rg1) s[nt][2] = -INFINITY;
                if (col0 + 1 > rg1) s[nt][3] = -INFINITY;
            }
            mx0 = fmaxf(mx0, fmaxf(s[nt][0], s[nt][1]));
            mx1 = fmaxf(mx1, fmaxf(s[nt][2], s[nt][3]));
        }
        mx0 = fmaxf(mx0, __shfl_xor_sync(0xffffffffu, mx0, 1));
        mx0 = fmaxf(mx0, __shfl_xor_sync(0xffffffffu, mx0, 2));
        mx1 = fmaxf(mx1, __shfl_xor_sync(0xffffffffu, mx1, 1));
        mx1 = fmaxf(mx1, __shfl_xor_sync(0xffffffffu, mx1, 2));

        float a0s = __expf(mr0 - mx0);   // exp(-inf)=0 handles first iter
        float a1s = __expf(mr1 - mx1);
        float sum0 = 0.f, sum1 = 0.f;
#pragma unroll
        for (int nt = 0; nt < 8; nt++) {
            float p0 = rtf32(__expf(s[nt][0] - mx0));
            float p1 = rtf32(__expf(s[nt][1] - mx0));
            float p2 = rtf32(__expf(s[nt][2] - mx1));
            float p3 = rtf32(__expf(s[nt][3] - mx1));
            s[nt][0] = p0; s[nt][1] = p1; s[nt][2] = p2; s[nt][3] = p3;
            sum0 += p0 + p1;
            sum1 += p2 + p3;
        }
        sum0 += __shfl_xor_sync(0xffffffffu, sum0, 1);
        sum0 += __shfl_xor_sync(0xffffffffu, sum0, 2);
        sum1 += __shfl_xor_sync(0xffffffffu, sum1, 1);
        sum1 += __shfl_xor_sync(0xffffffffu, sum1, 2);
        l0 = l0 * a0s + sum0;
        l1 = l1 * a1s + sum1;
#pragma unroll
        for (int nt = 0; nt < 8; nt++) {
            o[nt][0] *= a0s; o[nt][1] *= a0s;
            o[nt][2] *= a1s; o[nt][3] *= a1s;
        }
        mr0 = mx0; mr1 = mx1;

        // ---- P -> smem (per-warp band), then O += P V ----
        __syncwarp();
#pragma unroll
        for (int nt = 0; nt < 8; nt++) {
            *(float2*)&sQP[SW(lrow,     nt * 8 + 2 * c)] = make_float2(s[nt][0], s[nt][1]);
            *(float2*)&sQP[SW(lrow + 8, nt * 8 + 2 * c)] = make_float2(s[nt][2], s[nt][3]);
        }
        __syncwarp();
#pragma unroll
        for (int kc = 0; kc < 8; kc++) {
            uint32_t af[4];
            af[0] = __float_as_uint(sQP[SW(lrow,     kc * 8 + c)]);
            af[1] = __float_as_uint(sQP[SW(lrow + 8, kc * 8 + c)]);
            af[2] = __float_as_uint(sQP[SW(lrow,     kc * 8 + c + 4)]);
            af[3] = __float_as_uint(sQP[SW(lrow + 8, kc * 8 + c + 4)]);
#pragma unroll
            for (int nt = 0; nt < 8; nt++) {
                uint32_t bf[2];
                bf[0] = __float_as_uint(sVt[SW(nt * 8 + r, kc * 8 + c)]);
                bf[1] = __float_as_uint(sVt[SW(nt * 8 + r, kc * 8 + c + 4)]);
                mma_tf32(o[nt], af, bf);
            }
        }
        __syncthreads();
    }

    float i0 = 1.f / l0, i1 = 1.f / l1;
#pragma unroll
    for (int nt = 0; nt < 8; nt++) {
        *(float2*)&Ob[(size_t)rg0 * HD + nt * 8 + 2 * c] =
            make_float2(o[nt][0] * i0, o[nt][1] * i0);
        *(float2*)&Ob[(size_t)rg1 * HD + nt * 8 + 2 * c] =
            make_float2(o[nt][2] * i1, o[nt][3] * i1);
    }
}

extern "C" void kernel_launch(void* const* d_in, const int* in_sizes, int n_in,
                              void* d_out, int out_size)
{
    const float* x  = (const float*)d_in[0];
    const float* Wq = (const float*)d_in[1];
    const float* bq = (const float*)d_in[2];
    const float* Wk = (const float*)d_in[3];
    const float* bk = (const float*)d_in[4];
    const float* Wv = (const float*)d_in[5];
    const float* bv = (const float*)d_in[6];
    const float* Wo = (const float*)d_in[7];
    const float* bo = (const float*)d_in[8];
    float* out = (float*)d_out;

    dim3 gt(32, 32, 4);
    transpose_w<<<gt, dim3(32, 8)>>>(Wq, Wk, Wv, Wo);

    dim3 g1(DD / 128, (BB * TT) / 128, 3);
    gemm_tc<0><<<g1, 256>>>(x, bq, bk, bv, nullptr);

    dim3 g2(TT / 64, BB * HH);               // 32 x 64
    attn_tc<<<g2, 128>>>();

    dim3 g3(DD / 128, (BB * TT) / 128);
    gemm_tc<1><<<g3, 256>>>(nullptr, bo, nullptr, nullptr, out);
}